// round 14
// baseline (speedup 1.0000x reference)
#include <cuda_runtime.h>
#include <cuda_fp16.h>
#include <cstdint>

#define NNODES 100000
#define NEDGES 1600000

// ---------------- device scratch (zero-initialized at load; re-zeroed by k_agg40) ----------------
__device__ int    g_deg[NNODES];        // 0 on entry to each kernel_launch
__device__ int    g_ticket;             // 0 on entry
__device__ int    g_off[NNODES + 1];    // block-local exclusive scan (add g_bsum lazily)
__device__ int    g_bsum[128];
__device__ int    g_rank[NEDGES];       // per-edge slot within its dst bucket
__device__ int    g_csr[NEDGES];        // stores src*32 (pre-scaled row offset)
__device__ __half g_a1[(size_t)NNODES * 256];   // [x fp16 (0..127) | agg fp16 (128..255)]
__device__ __half g_w1t[128 * 256];             // W1 concat, transposed: [n][k]
__device__ __half g_w2t[80 * 128];              // W2 concat, transposed: [n][k]
__device__ float  g_s [(size_t)NNODES * 40];    // h1 @ W2_self + b2
__device__ __half g_t [(size_t)NNODES * 64];    // h1 @ W2_neigh (fp16, stride 64)

// ---------------- baseline-PTX MMA helpers ----------------
__device__ __forceinline__ uint32_t smem_to_u32(const void* p) {
    uint32_t a;
    asm("{ .reg .u64 t; cvta.to.shared.u64 t, %1; cvt.u32.u64 %0, t; }" : "=r"(a) : "l"(p));
    return a;
}
__device__ __forceinline__ void ldsm4(uint32_t* r, uint32_t addr) {
    asm volatile("ldmatrix.sync.aligned.m8n8.x4.shared.b16 {%0,%1,%2,%3}, [%4];"
        : "=r"(r[0]), "=r"(r[1]), "=r"(r[2]), "=r"(r[3]) : "r"(addr));
}
__device__ __forceinline__ void mma16816(float* d, const uint32_t* a, const uint32_t* b) {
    asm volatile("mma.sync.aligned.m16n8k16.row.col.f32.f16.f16.f32 "
        "{%0,%1,%2,%3}, {%4,%5,%6,%7}, {%8,%9}, {%0,%1,%2,%3};"
        : "+f"(d[0]), "+f"(d[1]), "+f"(d[2]), "+f"(d[3])
        : "r"(a[0]), "r"(a[1]), "r"(a[2]), "r"(a[3]), "r"(b[0]), "r"(b[1]));
}

// ---------------- fused prep + degree count (atomic also yields per-edge rank) ----------------
__global__ void k_prep_count(const float* __restrict__ x,
                             const float* __restrict__ W1s, const float* __restrict__ W1n,
                             const float* __restrict__ W2s, const float* __restrict__ W2n,
                             const int* __restrict__ dst, int n, int e) {
    int i = blockIdx.x * blockDim.x + threadIdx.x;
    if (i < e) g_rank[i] = atomicAdd(&g_deg[dst[i]], 1);
    if (i < n * 64) {
        int row = i >> 6, c2 = i & 63;
        float2 v = ((const float2*)x)[i];
        ((__half2*)g_a1)[(size_t)row * 128 + c2] = __float22half2_rn(v);
    }
    if (i < 128 * 256) {
        int nn = i >> 8, k = i & 255;
        float v = (k < 128) ? W1s[k * 128 + nn] : W1n[(k - 128) * 128 + nn];
        g_w1t[nn * 256 + k] = __float2half(v);
    } else if (i < 128 * 256 + 80 * 128) {
        int j = i - 128 * 256;
        int nn = j >> 7, k = j & 127;
        float v = (nn < 40) ? W2s[k * 40 + nn] : W2n[k * 40 + (nn - 40)];
        g_w2t[nn * 128 + k] = __float2half(v);
    }
}

// ---------------- single-kernel two-level scan (last block does level 2) ----------------
__global__ void k_scan(int nb, int n) {
    __shared__ int sh[1024];
    __shared__ int lastFlag;
    int t = threadIdx.x;
    int i = blockIdx.x * 1024 + t;
    int v = (i < n) ? g_deg[i] : 0;
    sh[t] = v;
    __syncthreads();
#pragma unroll
    for (int o = 1; o < 1024; o <<= 1) {
        int x = (t >= o) ? sh[t - o] : 0;
        __syncthreads();
        sh[t] += x;
        __syncthreads();
    }
    if (i < n) g_off[i] = sh[t] - v;   // exclusive, block-local
    if (t == 1023) {
        g_bsum[blockIdx.x] = sh[1023];
        __threadfence();
        int old = atomicAdd(&g_ticket, 1);
        lastFlag = (old == nb - 1);
    }
    __syncthreads();
    if (!lastFlag) return;

    __threadfence();   // acquire: see all g_bsum stores
    int v2 = 0;
    if (t < 128) {
        v2 = (t < nb) ? g_bsum[t] : 0;
        sh[t] = v2;
    }
    __syncthreads();
#pragma unroll
    for (int o = 1; o < 128; o <<= 1) {
        int x = 0;
        if (t < 128 && t >= o) x = sh[t - o];
        __syncthreads();
        if (t < 128) sh[t] += x;
        __syncthreads();
    }
    if (t < 128) g_bsum[t] = sh[t] - v2;                    // exclusive block offsets
    if (t == (n >> 10)) g_off[n] = sh[127] - (sh[t] - v2);  // sentinel
}

// ---------------- CSR fill: atomic-free (rank precomputed) ----------------
__global__ void k_fill(const int* __restrict__ src, const int* __restrict__ dst, int e) {
    int i = blockIdx.x * blockDim.x + threadIdx.x;
    if (i < e) {
        int d = dst[i];
        g_csr[g_off[d] + g_bsum[d >> 10] + g_rank[i]] = src[i] << 5;   // pre-scaled by 32
    }
}

// ---------------- mean aggregation over node range [nStart, nEnd) ----------------
__global__ void k_aggh(int nStart, int nEnd) {
    int w    = nStart + ((blockIdx.x * blockDim.x + threadIdx.x) >> 5);
    int lane = threadIdx.x & 31;
    if (w >= nEnd) return;
    int b  = g_off[w]     + g_bsum[w >> 10];
    int e2 = g_off[w + 1] + g_bsum[(w + 1) >> 10];
    const int half = lane >> 4;
    const int cl   = lane & 15;
    float2 a0 = make_float2(0.f, 0.f), a1 = make_float2(0.f, 0.f);
    float2 a2 = make_float2(0.f, 0.f), a3 = make_float2(0.f, 0.f);
    const uint4* __restrict__ base = (const uint4*)g_a1;   // row = 32 uint4 (csr pre-scaled)
    int i = b + half;
#pragma unroll 1
    for (; i + 6 < e2; i += 8) {           // 4 edges per half-lane iter
        int s0 = g_csr[i],     s1 = g_csr[i + 2];
        int s2 = g_csr[i + 4], s3 = g_csr[i + 6];
        uint4 r0 = base[s0 + cl];
        uint4 r1 = base[s1 + cl];
        uint4 r2 = base[s2 + cl];
        uint4 r3 = base[s3 + cl];
        const __half2* h0 = (const __half2*)&r0;
        const __half2* h1 = (const __half2*)&r1;
        const __half2* h2 = (const __half2*)&r2;
        const __half2* h3 = (const __half2*)&r3;
        __half2 p0 = __hadd2(__hadd2(h0[0], h1[0]), __hadd2(h2[0], h3[0]));
        __half2 p1 = __hadd2(__hadd2(h0[1], h1[1]), __hadd2(h2[1], h3[1]));
        __half2 p2 = __hadd2(__hadd2(h0[2], h1[2]), __hadd2(h2[2], h3[2]));
        __half2 p3 = __hadd2(__hadd2(h0[3], h1[3]), __hadd2(h2[3], h3[3]));
        float2 f0 = __half22float2(p0), f1 = __half22float2(p1);
        float2 f2 = __half22float2(p2), f3 = __half22float2(p3);
        a0.x += f0.x; a0.y += f0.y; a1.x += f1.x; a1.y += f1.y;
        a2.x += f2.x; a2.y += f2.y; a3.x += f3.x; a3.y += f3.y;
    }
#pragma unroll 1
    for (; i < e2; i += 2) {               // leftovers
        int s = g_csr[i];
        uint4 raw = base[s + cl];
        const __half2* h = (const __half2*)&raw;
        float2 f0 = __half22float2(h[0]), f1 = __half22float2(h[1]);
        float2 f2 = __half22float2(h[2]), f3 = __half22float2(h[3]);
        a0.x += f0.x; a0.y += f0.y; a1.x += f1.x; a1.y += f1.y;
        a2.x += f2.x; a2.y += f2.y; a3.x += f3.x; a3.y += f3.y;
    }
    a0.x += __shfl_xor_sync(0xffffffffu, a0.x, 16);
    a0.y += __shfl_xor_sync(0xffffffffu, a0.y, 16);
    a1.x += __shfl_xor_sync(0xffffffffu, a1.x, 16);
    a1.y += __shfl_xor_sync(0xffffffffu, a1.y, 16);
    a2.x += __shfl_xor_sync(0xffffffffu, a2.x, 16);
    a2.y += __shfl_xor_sync(0xffffffffu, a2.y, 16);
    a3.x += __shfl_xor_sync(0xffffffffu, a3.x, 16);
    a3.y += __shfl_xor_sync(0xffffffffu, a3.y, 16);
    if (half == 0) {
        float inv = 1.0f / (float)max(e2 - b, 1);
        __half2 h0 = __floats2half2_rn(a0.x * inv, a0.y * inv);
        __half2 h1 = __floats2half2_rn(a1.x * inv, a1.y * inv);
        __half2 h2 = __floats2half2_rn(a2.x * inv, a2.y * inv);
        __half2 h3 = __floats2half2_rn(a3.x * inv, a3.y * inv);
        uint4 o;
        o.x = *(uint32_t*)&h0; o.y = *(uint32_t*)&h1;
        o.z = *(uint32_t*)&h2; o.w = *(uint32_t*)&h3;
        ((uint4*)g_a1)[(size_t)w * 32 + 16 + cl] = o;   // agg-part (cols 128..255)
    }
}

// ---------------- fused GEMM (HMMA), 96KB smem for 2 CTAs/SM; row range via rowStart ----------------
__global__ __launch_bounds__(256, 2) void k_gemm_fused(
    const float* __restrict__ bias1, const float* __restrict__ bias2, int rowStart, int n)
{
    extern __shared__ __align__(16) char smem[];
    uint4* sA4 = (uint4*)smem;
    uint4* sB4 = (uint4*)(smem + 65536);   // 32KB region
    const int tid = threadIdx.x;
    const int rowBase = rowStart + blockIdx.x * 128;
    const int wid = tid >> 5, lane = tid & 31;
    const int wm = wid >> 2, wn = wid & 3;
    const uint32_t sAb = smem_to_u32(sA4), sBb = smem_to_u32(sB4);

    const uint4* a4 = (const uint4*)g_a1;
    for (int i = tid; i < 4096; i += 256) {
        int r = i >> 5, c = i & 31;
        uint4 v = make_uint4(0u, 0u, 0u, 0u);
        int gr = rowBase + r;
        if (gr < n) v = a4[(size_t)gr * 32 + c];
        sA4[r * 32 + (c ^ (r & 7))] = v;
    }

    float acc[4][4][4];
#pragma unroll
    for (int mt = 0; mt < 4; mt++)
#pragma unroll
        for (int nt = 0; nt < 4; nt++)
#pragma unroll
            for (int j = 0; j < 4; j++) acc[mt][nt][j] = 0.f;

    const int lr = lane & 7;
    const int lA_rhi = (lane >> 3) & 1, lA_chi = lane >> 4;
    const int lB_rhi = lane >> 4, lB_chi = (lane >> 3) & 1;
    const uint4* w14 = (const uint4*)g_w1t;

#pragma unroll 1
    for (int s = 0; s < 2; s++) {
        if (s) __syncthreads();
#pragma unroll 2
        for (int i = tid; i < 2048; i += 256) {
            int r = i >> 4, c = i & 15;
            sB4[r * 16 + (c ^ (r & 7))] = w14[r * 32 + s * 16 + c];
        }
        __syncthreads();
#pragma unroll 4
        for (int kk = 0; kk < 8; kk++) {
            int ks = s * 8 + kk;
            uint32_t afr[4][4];
#pragma unroll
            for (int mt = 0; mt < 4; mt++) {
                int r = wm * 64 + mt * 16 + lr + lA_rhi * 8;
                int c = 2 * ks + lA_chi;
                ldsm4(afr[mt], sAb + (uint32_t)(r * 32 + (c ^ (r & 7))) * 16);
            }
            uint32_t bfr[2][4];
#pragma unroll
            for (int np = 0; np < 2; np++) {
                int r = wn * 32 + np * 16 + lr + lB_rhi * 8;
                int c = 2 * kk + lB_chi;
                ldsm4(bfr[np], sBb + (uint32_t)(r * 16 + (c ^ (r & 7))) * 16);
            }
#pragma unroll
            for (int mt = 0; mt < 4; mt++)
#pragma unroll
                for (int nt = 0; nt < 4; nt++)
                    mma16816(acc[mt][nt], afr[mt], &bfr[nt >> 1][(nt & 1) * 2]);
        }
    }
    __syncthreads();

    const uint4* w24 = (const uint4*)g_w2t;
    for (int i = tid; i < 1280; i += 256) {
        int r = i >> 4, c = i & 15;
        sA4[r * 16 + (c ^ (r & 7))] = w24[r * 16 + c];
    }

    __half2* sH2 = (__half2*)sB4;
    const int qr = lane >> 2, qc = (lane & 3) * 2;
#pragma unroll
    for (int mt = 0; mt < 4; mt++) {
#pragma unroll
        for (int half_ = 0; half_ < 2; half_++) {
            int lrow = wm * 64 + mt * 16 + qr + half_ * 8;
#pragma unroll
            for (int nt = 0; nt < 4; nt++) {
                int col = wn * 32 + nt * 8 + qc;
                float f0 = fmaxf(acc[mt][nt][half_ * 2]     + __ldg(bias1 + col),     0.f);
                float f1 = fmaxf(acc[mt][nt][half_ * 2 + 1] + __ldg(bias1 + col + 1), 0.f);
                int cu = col >> 3;
                int h2idx = (lrow * 16 + (cu ^ (lrow & 7))) * 4 + ((col & 7) >> 1);
                sH2[h2idx] = __floats2half2_rn(f0, f1);
            }
        }
    }
    __syncthreads();

    float acc2[10][4];
#pragma unroll
    for (int nt = 0; nt < 10; nt++)
#pragma unroll
        for (int j = 0; j < 4; j++) acc2[nt][j] = 0.f;

#pragma unroll 4
    for (int ks = 0; ks < 8; ks++) {
        uint32_t afr[4];
        {
            int r = wid * 16 + lr + lA_rhi * 8;
            int c = 2 * ks + lA_chi;
            ldsm4(afr, sBb + (uint32_t)(r * 16 + (c ^ (r & 7))) * 16);
        }
        uint32_t bfr[5][4];
#pragma unroll
        for (int np = 0; np < 5; np++) {
            int r = np * 16 + lr + lB_rhi * 8;
            int c = 2 * ks + lB_chi;
            ldsm4(bfr[np], sAb + (uint32_t)(r * 16 + (c ^ (r & 7))) * 16);
        }
#pragma unroll
        for (int nt = 0; nt < 10; nt++)
            mma16816(acc2[nt], afr, &bfr[nt >> 1][(nt & 1) * 2]);
    }

#pragma unroll
    for (int half_ = 0; half_ < 2; half_++) {
        int row = rowBase + wid * 16 + qr + half_ * 8;
        if (row < n) {
#pragma unroll
            for (int nt = 0; nt < 5; nt++) {
                int col = nt * 8 + qc;
                float2 v;
                v.x = acc2[nt][half_ * 2]     + __ldg(bias2 + col);
                v.y = acc2[nt][half_ * 2 + 1] + __ldg(bias2 + col + 1);
                *(float2*)(g_s + (size_t)row * 40 + col) = v;
            }
#pragma unroll
            for (int nt = 5; nt < 10; nt++) {
                int col = (nt - 5) * 8 + qc;
                __half2 h = __floats2half2_rn(acc2[nt][half_ * 2], acc2[nt][half_ * 2 + 1]);
                *(__half2*)(g_t + (size_t)row * 64 + col) = h;
            }
        }
    }
}

// ---------------- final: out = s + mean_agg(t), 4-edge fp16 tree; re-zero counters ----------------
__global__ void k_agg40(float* __restrict__ out, int n) {
    int w    = (blockIdx.x * blockDim.x + threadIdx.x) >> 5;
    int lane = threadIdx.x & 31;
    if (w >= n) return;
    if (lane == 20) g_deg[w] = 0;
    if (lane == 21 && w == 0) g_ticket = 0;
    if (lane >= 20) return;
    int b  = g_off[w]     + g_bsum[w >> 10];
    int e2 = g_off[w + 1] + g_bsum[(w + 1) >> 10];
    float2 acc = make_float2(0.f, 0.f);
    const __half2* __restrict__ base = (const __half2*)g_t;   // row = 32 half2 (csr pre-scaled)
    int i = b;
#pragma unroll 1
    for (; i + 3 < e2; i += 4) {
        int s0 = g_csr[i],     s1 = g_csr[i + 1];
        int s2 = g_csr[i + 2], s3 = g_csr[i + 3];
        __half2 v0 = base[s0 + lane];
        __half2 v1 = base[s1 + lane];
        __half2 v2 = base[s2 + lane];
        __half2 v3 = base[s3 + lane];
        float2 f = __half22float2(__hadd2(__hadd2(v0, v1), __hadd2(v2, v3)));
        acc.x += f.x; acc.y += f.y;
    }
#pragma unroll 1
    for (; i < e2; i++) {
        int s = g_csr[i];
        float2 f = __half22float2(base[s + lane]);
        acc.x += f.x; acc.y += f.y;
    }
    float inv = 1.0f / (float)max(e2 - b, 1);
    float2 sv = ((const float2*)(g_s + (size_t)w * 40))[lane];
    float2 r = make_float2(sv.x + acc.x * inv, sv.y + acc.y * inv);
    ((float2*)(out + (size_t)w * 40))[lane] = r;
}

// ---------------- launch: stream-fork so aggh(half1) overlaps gemm(half0) ----------------
extern "C" void kernel_launch(void* const* d_in, const int* in_sizes, int n_in,
                              void* d_out, int out_size) {
    const float* x   = (const float*)d_in[0];
    const int*   src = (const int*)  d_in[1];
    const int*   dst = (const int*)  d_in[2];
    const float* W1s = (const float*)d_in[3];
    const float* W1n = (const float*)d_in[4];
    const float* b1  = (const float*)d_in[5];
    const float* W2s = (const float*)d_in[6];
    const float* W2n = (const float*)d_in[7];
    const float* b2  = (const float*)d_in[8];
    float* out = (float*)d_out;

    const int E = in_sizes[1];
    const int N = in_sizes[0] / 128;
    const int nb = (N + 1023) / 1024;
    const int N2 = ((N / 2) + 127) & ~127;   // tile-aligned split

    static cudaStream_t s_side = nullptr;
    static cudaEvent_t  s_evA = nullptr, s_evB = nullptr;
    if (!s_side) {
        cudaStreamCreateWithFlags(&s_side, cudaStreamNonBlocking);
        cudaEventCreateWithFlags(&s_evA, cudaEventDisableTiming);
        cudaEventCreateWithFlags(&s_evB, cudaEventDisableTiming);
    }

    cudaFuncSetAttribute(k_gemm_fused, cudaFuncAttributeMaxDynamicSharedMemorySize, 98304);

    k_prep_count<<<(N * 64 + 255) / 256, 256>>>(x, W1s, W1n, W2s, W2n, dst, N, E);
    k_scan<<<nb, 1024>>>(nb, N);
    k_fill<<<(E + 255) / 256, 256>>>(src, dst, E);

    k_aggh<<<(N2 + 7) / 8, 256>>>(0, N2);                       // half 0 (legacy)
    cudaEventRecord(s_evA, 0);
    cudaStreamWaitEvent(s_side, s_evA, 0);
    k_aggh<<<(N - N2 + 7) / 8, 256, 0, s_side>>>(N2, N);        // half 1 (side, overlaps gemm0)
    cudaEventRecord(s_evB, s_side);

    k_gemm_fused<<<N2 / 128, 256, 98304>>>(b1, b2, 0, N);       // rows [0, N2)
    cudaStreamWaitEvent(0, s_evB, 0);
    k_gemm_fused<<<(N - N2 + 127) / 128, 256, 98304>>>(b1, b2, N2, N);  // rows [N2, N)

    k_agg40<<<(N + 7) / 8, 256>>>(out, N);
}

// round 15
// speedup vs baseline: 1.2042x; 1.2042x over previous
#include <cuda_runtime.h>
#include <cuda_fp16.h>
#include <cstdint>

#define NNODES 100000
#define NEDGES 1600000

// ---------------- device scratch (zero-initialized at load; re-zeroed by k_agg40) ----------------
__device__ int    g_deg[NNODES];        // 0 on entry to each kernel_launch
__device__ int    g_ticket;             // 0 on entry
__device__ int    g_off[NNODES + 1];    // block-local exclusive scan (add g_bsum lazily)
__device__ int    g_bsum[128];
__device__ int    g_rank[NEDGES];       // per-edge slot within its dst bucket
__device__ int    g_csr[NEDGES];        // stores src*32 (pre-scaled row offset)
__device__ __half g_a1[(size_t)NNODES * 256];   // [x fp16 (0..127) | agg fp16 (128..255)]
__device__ __half g_w1t[128 * 256];             // W1 concat, transposed: [n][k]
__device__ __half g_w2t[80 * 128];              // W2 concat, transposed: [n][k]
__device__ float  g_s [(size_t)NNODES * 40];    // h1 @ W2_self + b2
__device__ __half g_t [(size_t)NNODES * 64];    // h1 @ W2_neigh (fp16, stride 64)

// ---------------- baseline-PTX MMA helpers ----------------
__device__ __forceinline__ uint32_t smem_to_u32(const void* p) {
    uint32_t a;
    asm("{ .reg .u64 t; cvta.to.shared.u64 t, %1; cvt.u32.u64 %0, t; }" : "=r"(a) : "l"(p));
    return a;
}
__device__ __forceinline__ void ldsm4(uint32_t* r, uint32_t addr) {
    asm volatile("ldmatrix.sync.aligned.m8n8.x4.shared.b16 {%0,%1,%2,%3}, [%4];"
        : "=r"(r[0]), "=r"(r[1]), "=r"(r[2]), "=r"(r[3]) : "r"(addr));
}
__device__ __forceinline__ void mma16816(float* d, const uint32_t* a, const uint32_t* b) {
    asm volatile("mma.sync.aligned.m16n8k16.row.col.f32.f16.f16.f32 "
        "{%0,%1,%2,%3}, {%4,%5,%6,%7}, {%8,%9}, {%0,%1,%2,%3};"
        : "+f"(d[0]), "+f"(d[1]), "+f"(d[2]), "+f"(d[3])
        : "r"(a[0]), "r"(a[1]), "r"(a[2]), "r"(a[3]), "r"(b[0]), "r"(b[1]));
}

// ---------------- fused prep + degree count (atomic also yields per-edge rank) ----------------
__global__ void k_prep_count(const float* __restrict__ x,
                             const float* __restrict__ W1s, const float* __restrict__ W1n,
                             const float* __restrict__ W2s, const float* __restrict__ W2n,
                             const int* __restrict__ dst, int n, int e) {
    int i = blockIdx.x * blockDim.x + threadIdx.x;
    if (i < e) g_rank[i] = atomicAdd(&g_deg[dst[i]], 1);
    if (i < n * 64) {
        int row = i >> 6, c2 = i & 63;
        float2 v = ((const float2*)x)[i];
        ((__half2*)g_a1)[(size_t)row * 128 + c2] = __float22half2_rn(v);
    }
    if (i < 128 * 256) {
        int nn = i >> 8, k = i & 255;
        float v = (k < 128) ? W1s[k * 128 + nn] : W1n[(k - 128) * 128 + nn];
        g_w1t[nn * 256 + k] = __float2half(v);
    } else if (i < 128 * 256 + 80 * 128) {
        int j = i - 128 * 256;
        int nn = j >> 7, k = j & 127;
        float v = (nn < 40) ? W2s[k * 40 + nn] : W2n[k * 40 + (nn - 40)];
        g_w2t[nn * 128 + k] = __float2half(v);
    }
}

// ---------------- single-kernel two-level scan (last block does level 2) ----------------
__global__ void k_scan(int nb, int n) {
    __shared__ int sh[1024];
    __shared__ int lastFlag;
    int t = threadIdx.x;
    int i = blockIdx.x * 1024 + t;
    int v = (i < n) ? g_deg[i] : 0;
    sh[t] = v;
    __syncthreads();
#pragma unroll
    for (int o = 1; o < 1024; o <<= 1) {
        int x = (t >= o) ? sh[t - o] : 0;
        __syncthreads();
        sh[t] += x;
        __syncthreads();
    }
    if (i < n) g_off[i] = sh[t] - v;   // exclusive, block-local
    if (t == 1023) {
        g_bsum[blockIdx.x] = sh[1023];
        __threadfence();
        int old = atomicAdd(&g_ticket, 1);
        lastFlag = (old == nb - 1);
    }
    __syncthreads();
    if (!lastFlag) return;

    __threadfence();   // acquire: see all g_bsum stores
    int v2 = 0;
    if (t < 128) {
        v2 = (t < nb) ? g_bsum[t] : 0;
        sh[t] = v2;
    }
    __syncthreads();
#pragma unroll
    for (int o = 1; o < 128; o <<= 1) {
        int x = 0;
        if (t < 128 && t >= o) x = sh[t - o];
        __syncthreads();
        if (t < 128) sh[t] += x;
        __syncthreads();
    }
    if (t < 128) g_bsum[t] = sh[t] - v2;                    // exclusive block offsets
    if (t == (n >> 10)) g_off[n] = sh[127] - (sh[t] - v2);  // sentinel
}

// ---------------- CSR fill: atomic-free (rank precomputed) ----------------
__global__ void k_fill(const int* __restrict__ src, const int* __restrict__ dst, int e) {
    int i = blockIdx.x * blockDim.x + threadIdx.x;
    if (i < e) {
        int d = dst[i];
        g_csr[g_off[d] + g_bsum[d >> 10] + g_rank[i]] = src[i] << 5;   // pre-scaled by 32
    }
}

// ---------------- mean aggregation: warp/node, 4-edge fp16 tree, uint4 loads ----------------
__global__ void k_aggh(int n) {
    int w    = (blockIdx.x * blockDim.x + threadIdx.x) >> 5;
    int lane = threadIdx.x & 31;
    if (w >= n) return;
    int b  = g_off[w]     + g_bsum[w >> 10];
    int e2 = g_off[w + 1] + g_bsum[(w + 1) >> 10];
    const int half = lane >> 4;
    const int cl   = lane & 15;
    float2 a0 = make_float2(0.f, 0.f), a1 = make_float2(0.f, 0.f);
    float2 a2 = make_float2(0.f, 0.f), a3 = make_float2(0.f, 0.f);
    const uint4* __restrict__ base = (const uint4*)g_a1;   // row = 32 uint4 (csr pre-scaled)
    int i = b + half;
#pragma unroll 1
    for (; i + 6 < e2; i += 8) {           // 4 edges per half-lane iter
        int s0 = g_csr[i],     s1 = g_csr[i + 2];
        int s2 = g_csr[i + 4], s3 = g_csr[i + 6];
        uint4 r0 = base[s0 + cl];
        uint4 r1 = base[s1 + cl];
        uint4 r2 = base[s2 + cl];
        uint4 r3 = base[s3 + cl];
        const __half2* h0 = (const __half2*)&r0;
        const __half2* h1 = (const __half2*)&r1;
        const __half2* h2 = (const __half2*)&r2;
        const __half2* h3 = (const __half2*)&r3;
        __half2 p0 = __hadd2(__hadd2(h0[0], h1[0]), __hadd2(h2[0], h3[0]));
        __half2 p1 = __hadd2(__hadd2(h0[1], h1[1]), __hadd2(h2[1], h3[1]));
        __half2 p2 = __hadd2(__hadd2(h0[2], h1[2]), __hadd2(h2[2], h3[2]));
        __half2 p3 = __hadd2(__hadd2(h0[3], h1[3]), __hadd2(h2[3], h3[3]));
        float2 f0 = __half22float2(p0), f1 = __half22float2(p1);
        float2 f2 = __half22float2(p2), f3 = __half22float2(p3);
        a0.x += f0.x; a0.y += f0.y; a1.x += f1.x; a1.y += f1.y;
        a2.x += f2.x; a2.y += f2.y; a3.x += f3.x; a3.y += f3.y;
    }
#pragma unroll 1
    for (; i < e2; i += 2) {               // leftovers
        int s = g_csr[i];
        uint4 raw = base[s + cl];
        const __half2* h = (const __half2*)&raw;
        float2 f0 = __half22float2(h[0]), f1 = __half22float2(h[1]);
        float2 f2 = __half22float2(h[2]), f3 = __half22float2(h[3]);
        a0.x += f0.x; a0.y += f0.y; a1.x += f1.x; a1.y += f1.y;
        a2.x += f2.x; a2.y += f2.y; a3.x += f3.x; a3.y += f3.y;
    }
    a0.x += __shfl_xor_sync(0xffffffffu, a0.x, 16);
    a0.y += __shfl_xor_sync(0xffffffffu, a0.y, 16);
    a1.x += __shfl_xor_sync(0xffffffffu, a1.x, 16);
    a1.y += __shfl_xor_sync(0xffffffffu, a1.y, 16);
    a2.x += __shfl_xor_sync(0xffffffffu, a2.x, 16);
    a2.y += __shfl_xor_sync(0xffffffffu, a2.y, 16);
    a3.x += __shfl_xor_sync(0xffffffffu, a3.x, 16);
    a3.y += __shfl_xor_sync(0xffffffffu, a3.y, 16);
    if (half == 0) {
        float inv = 1.0f / (float)max(e2 - b, 1);
        __half2 h0 = __floats2half2_rn(a0.x * inv, a0.y * inv);
        __half2 h1 = __floats2half2_rn(a1.x * inv, a1.y * inv);
        __half2 h2 = __floats2half2_rn(a2.x * inv, a2.y * inv);
        __half2 h3 = __floats2half2_rn(a3.x * inv, a3.y * inv);
        uint4 o;
        o.x = *(uint32_t*)&h0; o.y = *(uint32_t*)&h1;
        o.z = *(uint32_t*)&h2; o.w = *(uint32_t*)&h3;
        ((uint4*)g_a1)[(size_t)w * 32 + 16 + cl] = o;   // agg-part (cols 128..255)
    }
}

// ---------------- fused GEMM (HMMA), 96KB smem for 2 CTAs/SM ----------------
__global__ __launch_bounds__(256, 2) void k_gemm_fused(
    const float* __restrict__ bias1, const float* __restrict__ bias2, int n)
{
    extern __shared__ __align__(16) char smem[];
    uint4* sA4 = (uint4*)smem;
    uint4* sB4 = (uint4*)(smem + 65536);   // 32KB region
    const int tid = threadIdx.x;
    const int rowBase = blockIdx.x * 128;
    const int wid = tid >> 5, lane = tid & 31;
    const int wm = wid >> 2, wn = wid & 3;
    const uint32_t sAb = smem_to_u32(sA4), sBb = smem_to_u32(sB4);

    const uint4* a4 = (const uint4*)g_a1;
    for (int i = tid; i < 4096; i += 256) {
        int r = i >> 5, c = i & 31;
        uint4 v = make_uint4(0u, 0u, 0u, 0u);
        int gr = rowBase + r;
        if (gr < n) v = a4[(size_t)gr * 32 + c];
        sA4[r * 32 + (c ^ (r & 7))] = v;
    }

    float acc[4][4][4];
#pragma unroll
    for (int mt = 0; mt < 4; mt++)
#pragma unroll
        for (int nt = 0; nt < 4; nt++)
#pragma unroll
            for (int j = 0; j < 4; j++) acc[mt][nt][j] = 0.f;

    const int lr = lane & 7;
    const int lA_rhi = (lane >> 3) & 1, lA_chi = lane >> 4;
    const int lB_rhi = lane >> 4, lB_chi = (lane >> 3) & 1;
    const uint4* w14 = (const uint4*)g_w1t;

#pragma unroll 1
    for (int s = 0; s < 2; s++) {
        if (s) __syncthreads();
#pragma unroll 2
        for (int i = tid; i < 2048; i += 256) {
            int r = i >> 4, c = i & 15;
            sB4[r * 16 + (c ^ (r & 7))] = w14[r * 32 + s * 16 + c];
        }
        __syncthreads();
#pragma unroll 4
        for (int kk = 0; kk < 8; kk++) {
            int ks = s * 8 + kk;
            uint32_t afr[4][4];
#pragma unroll
            for (int mt = 0; mt < 4; mt++) {
                int r = wm * 64 + mt * 16 + lr + lA_rhi * 8;
                int c = 2 * ks + lA_chi;
                ldsm4(afr[mt], sAb + (uint32_t)(r * 32 + (c ^ (r & 7))) * 16);
            }
            uint32_t bfr[2][4];
#pragma unroll
            for (int np = 0; np < 2; np++) {
                int r = wn * 32 + np * 16 + lr + lB_rhi * 8;
                int c = 2 * kk + lB_chi;
                ldsm4(bfr[np], sBb + (uint32_t)(r * 16 + (c ^ (r & 7))) * 16);
            }
#pragma unroll
            for (int mt = 0; mt < 4; mt++)
#pragma unroll
                for (int nt = 0; nt < 4; nt++)
                    mma16816(acc[mt][nt], afr[mt], &bfr[nt >> 1][(nt & 1) * 2]);
        }
    }
    __syncthreads();

    const uint4* w24 = (const uint4*)g_w2t;
    for (int i = tid; i < 1280; i += 256) {
        int r = i >> 4, c = i & 15;
        sA4[r * 16 + (c ^ (r & 7))] = w24[r * 16 + c];
    }

    __half2* sH2 = (__half2*)sB4;
    const int qr = lane >> 2, qc = (lane & 3) * 2;
#pragma unroll
    for (int mt = 0; mt < 4; mt++) {
#pragma unroll
        for (int half_ = 0; half_ < 2; half_++) {
            int lrow = wm * 64 + mt * 16 + qr + half_ * 8;
#pragma unroll
            for (int nt = 0; nt < 4; nt++) {
                int col = wn * 32 + nt * 8 + qc;
                float f0 = fmaxf(acc[mt][nt][half_ * 2]     + __ldg(bias1 + col),     0.f);
                float f1 = fmaxf(acc[mt][nt][half_ * 2 + 1] + __ldg(bias1 + col + 1), 0.f);
                int cu = col >> 3;
                int h2idx = (lrow * 16 + (cu ^ (lrow & 7))) * 4 + ((col & 7) >> 1);
                sH2[h2idx] = __floats2half2_rn(f0, f1);
            }
        }
    }
    __syncthreads();

    float acc2[10][4];
#pragma unroll
    for (int nt = 0; nt < 10; nt++)
#pragma unroll
        for (int j = 0; j < 4; j++) acc2[nt][j] = 0.f;

#pragma unroll 4
    for (int ks = 0; ks < 8; ks++) {
        uint32_t afr[4];
        {
            int r = wid * 16 + lr + lA_rhi * 8;
            int c = 2 * ks + lA_chi;
            ldsm4(afr, sBb + (uint32_t)(r * 16 + (c ^ (r & 7))) * 16);
        }
        uint32_t bfr[5][4];
#pragma unroll
        for (int np = 0; np < 5; np++) {
            int r = np * 16 + lr + lB_rhi * 8;
            int c = 2 * ks + lB_chi;
            ldsm4(bfr[np], sAb + (uint32_t)(r * 16 + (c ^ (r & 7))) * 16);
        }
#pragma unroll
        for (int nt = 0; nt < 10; nt++)
            mma16816(acc2[nt], afr, &bfr[nt >> 1][(nt & 1) * 2]);
    }

#pragma unroll
    for (int half_ = 0; half_ < 2; half_++) {
        int row = rowBase + wid * 16 + qr + half_ * 8;
        if (row < n) {
#pragma unroll
            for (int nt = 0; nt < 5; nt++) {
                int col = nt * 8 + qc;
                float2 v;
                v.x = acc2[nt][half_ * 2]     + __ldg(bias2 + col);
                v.y = acc2[nt][half_ * 2 + 1] + __ldg(bias2 + col + 1);
                *(float2*)(g_s + (size_t)row * 40 + col) = v;
            }
#pragma unroll
            for (int nt = 5; nt < 10; nt++) {
                int col = (nt - 5) * 8 + qc;
                __half2 h = __floats2half2_rn(acc2[nt][half_ * 2], acc2[nt][half_ * 2 + 1]);
                *(__half2*)(g_t + (size_t)row * 64 + col) = h;
            }
        }
    }
}

// ---------------- final: out = s + mean_agg(t); 6 nodes per warp, 5 lanes each ----------------
__global__ void k_agg40(float* __restrict__ out, int n) {
    int warp  = (blockIdx.x * blockDim.x + threadIdx.x) >> 5;
    int lane  = threadIdx.x & 31;
    int group = lane / 5;          // 0..5 active, 6 for lanes 30..31
    int j     = lane - group * 5;  // uint4 column within 80B row
    int w = warp * 6 + group;
    // counter re-zero for next invocation (spare + j==0 lanes)
    if (group < 6 && w < n && j == 0) g_deg[w] = 0;
    if (warp == 0 && lane == 30) g_ticket = 0;
    if (group >= 6 || w >= n) return;

    int b  = g_off[w]     + g_bsum[w >> 10];
    int e2 = g_off[w + 1] + g_bsum[(w + 1) >> 10];
    float f0 = 0.f, f1 = 0.f, f2 = 0.f, f3 = 0.f;
    float f4 = 0.f, f5 = 0.f, f6 = 0.f, f7 = 0.f;
    const uint4* __restrict__ tb = (const uint4*)g_t;   // row = 8 uint4 (csr>>2)
    int i = b;
#pragma unroll 1
    for (; i + 1 < e2; i += 2) {
        int s0 = g_csr[i] >> 2, s1 = g_csr[i + 1] >> 2;
        uint4 r0 = tb[s0 + j];
        uint4 r1 = tb[s1 + j];
        const __half2* h0 = (const __half2*)&r0;
        const __half2* h1 = (const __half2*)&r1;
        float2 q0 = __half22float2(__hadd2(h0[0], h1[0]));
        float2 q1 = __half22float2(__hadd2(h0[1], h1[1]));
        float2 q2 = __half22float2(__hadd2(h0[2], h1[2]));
        float2 q3 = __half22float2(__hadd2(h0[3], h1[3]));
        f0 += q0.x; f1 += q0.y; f2 += q1.x; f3 += q1.y;
        f4 += q2.x; f5 += q2.y; f6 += q3.x; f7 += q3.y;
    }
    if (i < e2) {
        uint4 r0 = tb[(g_csr[i] >> 2) + j];
        const __half2* h0 = (const __half2*)&r0;
        float2 q0 = __half22float2(h0[0]);
        float2 q1 = __half22float2(h0[1]);
        float2 q2 = __half22float2(h0[2]);
        float2 q3 = __half22float2(h0[3]);
        f0 += q0.x; f1 += q0.y; f2 += q1.x; f3 += q1.y;
        f4 += q2.x; f5 += q2.y; f6 += q3.x; f7 += q3.y;
    }
    float inv = 1.0f / (float)max(e2 - b, 1);
    const float* sp = g_s + (size_t)w * 40 + j * 8;
    float4 s0 = *(const float4*)sp;
    float4 s1 = *(const float4*)(sp + 4);
    float4 o0, o1;
    o0.x = s0.x + f0 * inv; o0.y = s0.y + f1 * inv;
    o0.z = s0.z + f2 * inv; o0.w = s0.w + f3 * inv;
    o1.x = s1.x + f4 * inv; o1.y = s1.y + f5 * inv;
    o1.z = s1.z + f6 * inv; o1.w = s1.w + f7 * inv;
    float* op = out + (size_t)w * 40 + j * 8;
    *(float4*)op = o0;
    *(float4*)(op + 4) = o1;
}

// ---------------- launch (single stream; overlap proved harmful in R14) ----------------
extern "C" void kernel_launch(void* const* d_in, const int* in_sizes, int n_in,
                              void* d_out, int out_size) {
    const float* x   = (const float*)d_in[0];
    const int*   src = (const int*)  d_in[1];
    const int*   dst = (const int*)  d_in[2];
    const float* W1s = (const float*)d_in[3];
    const float* W1n = (const float*)d_in[4];
    const float* b1  = (const float*)d_in[5];
    const float* W2s = (const float*)d_in[6];
    const float* W2n = (const float*)d_in[7];
    const float* b2  = (const float*)d_in[8];
    float* out = (float*)d_out;

    const int E = in_sizes[1];
    const int N = in_sizes[0] / 128;
    const int nb = (N + 1023) / 1024;

    cudaFuncSetAttribute(k_gemm_fused, cudaFuncAttributeMaxDynamicSharedMemorySize, 98304);

    k_prep_count<<<(N * 64 + 255) / 256, 256>>>(x, W1s, W1n, W2s, W2n, dst, N, E);
    k_scan<<<nb, 1024>>>(nb, N);
    k_fill<<<(E + 255) / 256, 256>>>(src, dst, E);
    k_aggh<<<(N + 7) / 8, 256>>>(N);
    k_gemm_fused<<<(N + 127) / 128, 256, 98304>>>(b1, b2, N);
    k_agg40<<<((N + 5) / 6 * 32 + 255) / 256, 256>>>(out, N);
}

// round 16
// speedup vs baseline: 1.3302x; 1.1046x over previous
#include <cuda_runtime.h>
#include <cuda_fp16.h>
#include <cstdint>

#define NNODES 100000
#define NEDGES 1600000

// ---------------- device scratch (zero-initialized at load; re-zeroed by k_agg40) ----------------
__device__ int    g_deg[NNODES];        // 0 on entry to each kernel_launch
__device__ int    g_ticket;             // 0 on entry
__device__ int    g_off[NNODES + 1];    // block-local exclusive scan (add g_bsum lazily)
__device__ int    g_bsum[128];
__device__ int    g_rank[NEDGES];       // per-edge slot within its dst bucket
__device__ int    g_csr[NEDGES];        // stores src*32 (pre-scaled row offset)
__device__ __half g_a1[(size_t)NNODES * 256];   // [x fp16 (0..127) | agg fp16 (128..255)]
__device__ __half g_w1t[128 * 256];             // W1 concat, transposed: [n][k]
__device__ __half g_w2t[80 * 128];              // W2 concat, transposed: [n][k]
__device__ float  g_s [(size_t)NNODES * 40];    // h1 @ W2_self + b2
__device__ __half g_t [(size_t)NNODES * 64];    // h1 @ W2_neigh (fp16, stride 64)

// ---------------- baseline-PTX MMA helpers ----------------
__device__ __forceinline__ uint32_t smem_to_u32(const void* p) {
    uint32_t a;
    asm("{ .reg .u64 t; cvta.to.shared.u64 t, %1; cvt.u32.u64 %0, t; }" : "=r"(a) : "l"(p));
    return a;
}
__device__ __forceinline__ void ldsm4(uint32_t* r, uint32_t addr) {
    asm volatile("ldmatrix.sync.aligned.m8n8.x4.shared.b16 {%0,%1,%2,%3}, [%4];"
        : "=r"(r[0]), "=r"(r[1]), "=r"(r[2]), "=r"(r[3]) : "r"(addr));
}
__device__ __forceinline__ void mma16816(float* d, const uint32_t* a, const uint32_t* b) {
    asm volatile("mma.sync.aligned.m16n8k16.row.col.f32.f16.f16.f32 "
        "{%0,%1,%2,%3}, {%4,%5,%6,%7}, {%8,%9}, {%0,%1,%2,%3};"
        : "+f"(d[0]), "+f"(d[1]), "+f"(d[2]), "+f"(d[3])
        : "r"(a[0]), "r"(a[1]), "r"(a[2]), "r"(a[3]), "r"(b[0]), "r"(b[1]));
}

// ---------------- fused prep + degree count (atomic also yields per-edge rank) ----------------
__global__ void k_prep_count(const float* __restrict__ x,
                             const float* __restrict__ W1s, const float* __restrict__ W1n,
                             const float* __restrict__ W2s, const float* __restrict__ W2n,
                             const int* __restrict__ dst, int n, int e) {
    int i = blockIdx.x * blockDim.x + threadIdx.x;
    if (i < e) g_rank[i] = atomicAdd(&g_deg[dst[i]], 1);
    if (i < n * 32) {   // float4-vectorized x -> fp16
        int row = i >> 5, c4 = i & 31;
        float4 v = ((const float4*)x)[i];
        __half2 h0 = __floats2half2_rn(v.x, v.y);
        __half2 h1 = __floats2half2_rn(v.z, v.w);
        uint2 o;
        o.x = *(uint32_t*)&h0; o.y = *(uint32_t*)&h1;
        ((uint2*)g_a1)[(size_t)row * 64 + c4] = o;
    }
    if (i < 128 * 256) {
        int nn = i >> 8, k = i & 255;
        float v = (k < 128) ? W1s[k * 128 + nn] : W1n[(k - 128) * 128 + nn];
        g_w1t[nn * 256 + k] = __float2half(v);
    } else if (i < 128 * 256 + 80 * 128) {
        int j = i - 128 * 256;
        int nn = j >> 7, k = j & 127;
        float v = (nn < 40) ? W2s[k * 40 + nn] : W2n[k * 40 + (nn - 40)];
        g_w2t[nn * 128 + k] = __float2half(v);
    }
}

// ---------------- single-kernel two-level scan (last block does level 2) ----------------
__global__ void k_scan(int nb, int n) {
    __shared__ int sh[1024];
    __shared__ int lastFlag;
    int t = threadIdx.x;
    int i = blockIdx.x * 1024 + t;
    int v = (i < n) ? g_deg[i] : 0;
    sh[t] = v;
    __syncthreads();
#pragma unroll
    for (int o = 1; o < 1024; o <<= 1) {
        int x = (t >= o) ? sh[t - o] : 0;
        __syncthreads();
        sh[t] += x;
        __syncthreads();
    }
    if (i < n) g_off[i] = sh[t] - v;   // exclusive, block-local
    if (t == 1023) {
        g_bsum[blockIdx.x] = sh[1023];
        __threadfence();
        int old = atomicAdd(&g_ticket, 1);
        lastFlag = (old == nb - 1);
    }
    __syncthreads();
    if (!lastFlag) return;

    __threadfence();   // acquire: see all g_bsum stores
    int v2 = 0;
    if (t < 128) {
        v2 = (t < nb) ? g_bsum[t] : 0;
        sh[t] = v2;
    }
    __syncthreads();
#pragma unroll
    for (int o = 1; o < 128; o <<= 1) {
        int x = 0;
        if (t < 128 && t >= o) x = sh[t - o];
        __syncthreads();
        if (t < 128) sh[t] += x;
        __syncthreads();
    }
    if (t < 128) g_bsum[t] = sh[t] - v2;                    // exclusive block offsets
    if (t == (n >> 10)) g_off[n] = sh[127] - (sh[t] - v2);  // sentinel
}

// ---------------- CSR fill: atomic-free (rank precomputed) ----------------
__global__ void k_fill(const int* __restrict__ src, const int* __restrict__ dst, int e) {
    int i = blockIdx.x * blockDim.x + threadIdx.x;
    if (i < e) {
        int d = dst[i];
        g_csr[g_off[d] + g_bsum[d >> 10] + g_rank[i]] = src[i] << 5;   // pre-scaled by 32
    }
}

// ---------------- mean aggregation: warp/node, 4-edge fp16 tree, uint4 loads ----------------
__global__ void k_aggh(int n) {
    int w    = (blockIdx.x * blockDim.x + threadIdx.x) >> 5;
    int lane = threadIdx.x & 31;
    if (w >= n) return;
    int b  = g_off[w]     + g_bsum[w >> 10];
    int e2 = g_off[w + 1] + g_bsum[(w + 1) >> 10];
    const int half = lane >> 4;
    const int cl   = lane & 15;
    float2 a0 = make_float2(0.f, 0.f), a1 = make_float2(0.f, 0.f);
    float2 a2 = make_float2(0.f, 0.f), a3 = make_float2(0.f, 0.f);
    const uint4* __restrict__ base = (const uint4*)g_a1;   // row = 32 uint4 (csr pre-scaled)
    int i = b + half;
#pragma unroll 1
    for (; i + 6 < e2; i += 8) {           // 4 edges per half-lane iter
        int s0 = g_csr[i],     s1 = g_csr[i + 2];
        int s2 = g_csr[i + 4], s3 = g_csr[i + 6];
        uint4 r0 = base[s0 + cl];
        uint4 r1 = base[s1 + cl];
        uint4 r2 = base[s2 + cl];
        uint4 r3 = base[s3 + cl];
        const __half2* h0 = (const __half2*)&r0;
        const __half2* h1 = (const __half2*)&r1;
        const __half2* h2 = (const __half2*)&r2;
        const __half2* h3 = (const __half2*)&r3;
        __half2 p0 = __hadd2(__hadd2(h0[0], h1[0]), __hadd2(h2[0], h3[0]));
        __half2 p1 = __hadd2(__hadd2(h0[1], h1[1]), __hadd2(h2[1], h3[1]));
        __half2 p2 = __hadd2(__hadd2(h0[2], h1[2]), __hadd2(h2[2], h3[2]));
        __half2 p3 = __hadd2(__hadd2(h0[3], h1[3]), __hadd2(h2[3], h3[3]));
        float2 f0 = __half22float2(p0), f1 = __half22float2(p1);
        float2 f2 = __half22float2(p2), f3 = __half22float2(p3);
        a0.x += f0.x; a0.y += f0.y; a1.x += f1.x; a1.y += f1.y;
        a2.x += f2.x; a2.y += f2.y; a3.x += f3.x; a3.y += f3.y;
    }
#pragma unroll 1
    for (; i < e2; i += 2) {               // leftovers
        int s = g_csr[i];
        uint4 raw = base[s + cl];
        const __half2* h = (const __half2*)&raw;
        float2 f0 = __half22float2(h[0]), f1 = __half22float2(h[1]);
        float2 f2 = __half22float2(h[2]), f3 = __half22float2(h[3]);
        a0.x += f0.x; a0.y += f0.y; a1.x += f1.x; a1.y += f1.y;
        a2.x += f2.x; a2.y += f2.y; a3.x += f3.x; a3.y += f3.y;
    }
    a0.x += __shfl_xor_sync(0xffffffffu, a0.x, 16);
    a0.y += __shfl_xor_sync(0xffffffffu, a0.y, 16);
    a1.x += __shfl_xor_sync(0xffffffffu, a1.x, 16);
    a1.y += __shfl_xor_sync(0xffffffffu, a1.y, 16);
    a2.x += __shfl_xor_sync(0xffffffffu, a2.x, 16);
    a2.y += __shfl_xor_sync(0xffffffffu, a2.y, 16);
    a3.x += __shfl_xor_sync(0xffffffffu, a3.x, 16);
    a3.y += __shfl_xor_sync(0xffffffffu, a3.y, 16);
    if (half == 0) {
        float inv = 1.0f / (float)max(e2 - b, 1);
        __half2 h0 = __floats2half2_rn(a0.x * inv, a0.y * inv);
        __half2 h1 = __floats2half2_rn(a1.x * inv, a1.y * inv);
        __half2 h2 = __floats2half2_rn(a2.x * inv, a2.y * inv);
        __half2 h3 = __floats2half2_rn(a3.x * inv, a3.y * inv);
        uint4 o;
        o.x = *(uint32_t*)&h0; o.y = *(uint32_t*)&h1;
        o.z = *(uint32_t*)&h2; o.w = *(uint32_t*)&h3;
        ((uint4*)g_a1)[(size_t)w * 32 + 16 + cl] = o;   // agg-part (cols 128..255)
    }
}

// ---------------- fused GEMM (HMMA): 512 threads, 16 warps, 2 CTAs/SM (32 warps/SM) ----------------
// Phase 1: 4x4 warp grid, warp tile 32x32, K=256 via 2 W1 slices.
// Phase 2: warp -> (16-row tile, 40-col half); nh=0 writes g_s, nh=1 writes g_t.
__global__ __launch_bounds__(512, 2) void k_gemm_fused(
    const float* __restrict__ bias1, const float* __restrict__ bias2, int n)
{
    extern __shared__ __align__(16) char smem[];
    uint4* sA4 = (uint4*)smem;             // 64KB: A tile (later W2)
    uint4* sB4 = (uint4*)(smem + 65536);   // 32KB: W1 slice (later h1)
    const int tid = threadIdx.x;
    const int rowBase = blockIdx.x * 128;
    const int wid = tid >> 5, lane = tid & 31;
    const int wm = wid >> 2, wn = wid & 3;
    const uint32_t sAb = smem_to_u32(sA4), sBb = smem_to_u32(sB4);

    const uint4* a4 = (const uint4*)g_a1;
#pragma unroll 2
    for (int i = tid; i < 4096; i += 512) {
        int r = i >> 5, c = i & 31;
        uint4 v = make_uint4(0u, 0u, 0u, 0u);
        int gr = rowBase + r;
        if (gr < n) v = a4[(size_t)gr * 32 + c];
        sA4[r * 32 + (c ^ (r & 7))] = v;
    }

    float acc[2][4][4];
#pragma unroll
    for (int mt = 0; mt < 2; mt++)
#pragma unroll
        for (int nt = 0; nt < 4; nt++)
#pragma unroll
            for (int j = 0; j < 4; j++) acc[mt][nt][j] = 0.f;

    const int lr = lane & 7;
    const int lA_rhi = (lane >> 3) & 1, lA_chi = lane >> 4;
    const int lB_rhi = lane >> 4, lB_chi = (lane >> 3) & 1;
    const uint4* w14 = (const uint4*)g_w1t;

#pragma unroll 1
    for (int s = 0; s < 2; s++) {
        if (s) __syncthreads();
#pragma unroll
        for (int i = tid; i < 2048; i += 512) {
            int r = i >> 4, c = i & 15;
            sB4[r * 16 + (c ^ (r & 7))] = w14[r * 32 + s * 16 + c];
        }
        __syncthreads();
#pragma unroll 4
        for (int kk = 0; kk < 8; kk++) {
            int ks = s * 8 + kk;
            uint32_t afr[2][4];
#pragma unroll
            for (int mt = 0; mt < 2; mt++) {
                int r = wm * 32 + mt * 16 + lr + lA_rhi * 8;
                int c = 2 * ks + lA_chi;
                ldsm4(afr[mt], sAb + (uint32_t)(r * 32 + (c ^ (r & 7))) * 16);
            }
            uint32_t bfr[2][4];
#pragma unroll
            for (int np = 0; np < 2; np++) {
                int r = wn * 32 + np * 16 + lr + lB_rhi * 8;
                int c = 2 * kk + lB_chi;
                ldsm4(bfr[np], sBb + (uint32_t)(r * 16 + (c ^ (r & 7))) * 16);
            }
#pragma unroll
            for (int mt = 0; mt < 2; mt++)
#pragma unroll
                for (int nt = 0; nt < 4; nt++)
                    mma16816(acc[mt][nt], afr[mt], &bfr[nt >> 1][(nt & 1) * 2]);
        }
    }
    __syncthreads();

    // W2 into freed A region
    const uint4* w24 = (const uint4*)g_w2t;
#pragma unroll
    for (int i = tid; i < 1280; i += 512) {
        int r = i >> 4, c = i & 15;
        sA4[r * 16 + (c ^ (r & 7))] = w24[r * 16 + c];
    }

    // h1 (bias+relu, fp16) into freed W1 region
    __half2* sH2 = (__half2*)sB4;
    const int qr = lane >> 2, qc = (lane & 3) * 2;
#pragma unroll
    for (int mt = 0; mt < 2; mt++) {
#pragma unroll
        for (int half_ = 0; half_ < 2; half_++) {
            int lrow = wm * 32 + mt * 16 + qr + half_ * 8;
#pragma unroll
            for (int nt = 0; nt < 4; nt++) {
                int col = wn * 32 + nt * 8 + qc;
                float f0 = fmaxf(acc[mt][nt][half_ * 2]     + __ldg(bias1 + col),     0.f);
                float f1 = fmaxf(acc[mt][nt][half_ * 2 + 1] + __ldg(bias1 + col + 1), 0.f);
                int cu = col >> 3;
                int h2idx = (lrow * 16 + (cu ^ (lrow & 7))) * 4 + ((col & 7) >> 1);
                sH2[h2idx] = __floats2half2_rn(f0, f1);
            }
        }
    }
    __syncthreads();

    // ---- phase 2: warp wid -> rows (wid>>1)*16..+16, col-half (wid&1)*40..+40 ----
    const int mt2 = wid >> 1, nh = wid & 1;
    float acc2[5][4];
#pragma unroll
    for (int nt = 0; nt < 5; nt++)
#pragma unroll
        for (int j = 0; j < 4; j++) acc2[nt][j] = 0.f;

#pragma unroll 4
    for (int ks = 0; ks < 8; ks++) {
        uint32_t afr[4];
        {
            int r = mt2 * 16 + lr + lA_rhi * 8;
            int c = 2 * ks + lA_chi;
            ldsm4(afr, sBb + (uint32_t)(r * 16 + (c ^ (r & 7))) * 16);
        }
        uint32_t bfr[3][4];
#pragma unroll
        for (int np = 0; np < 3; np++) {
            int r = nh * 40 + np * 16 + lr + lB_rhi * 8;
            int c = 2 * ks + lB_chi;
            ldsm4(bfr[np], sAb + (uint32_t)(r * 16 + (c ^ (r & 7))) * 16);
        }
#pragma unroll
        for (int nt = 0; nt < 5; nt++)
            mma16816(acc2[nt], afr, &bfr[nt >> 1][(nt & 1) * 2]);
    }

#pragma unroll
    for (int half_ = 0; half_ < 2; half_++) {
        int row = rowBase + mt2 * 16 + qr + half_ * 8;
        if (row < n) {
            if (nh == 0) {      // self -> g_s fp32 + bias2
#pragma unroll
                for (int nt = 0; nt < 5; nt++) {
                    int col = nt * 8 + qc;
                    float2 v;
                    v.x = acc2[nt][half_ * 2]     + __ldg(bias2 + col);
                    v.y = acc2[nt][half_ * 2 + 1] + __ldg(bias2 + col + 1);
                    *(float2*)(g_s + (size_t)row * 40 + col) = v;
                }
            } else {            // neigh -> g_t fp16 (stride 64)
#pragma unroll
                for (int nt = 0; nt < 5; nt++) {
                    int col = nt * 8 + qc;
                    __half2 h = __floats2half2_rn(acc2[nt][half_ * 2], acc2[nt][half_ * 2 + 1]);
                    *(__half2*)(g_t + (size_t)row * 64 + col) = h;
                }
            }
        }
    }
}

// ---------------- final: out = s + mean_agg(t); 6 nodes per warp, 5 lanes each ----------------
__global__ void k_agg40(float* __restrict__ out, int n) {
    int warp  = (blockIdx.x * blockDim.x + threadIdx.x) >> 5;
    int lane  = threadIdx.x & 31;
    int group = lane / 5;          // 0..5 active, 6 for lanes 30..31
    int j     = lane - group * 5;  // uint4 column within 80B row
    int w = warp * 6 + group;
    if (group < 6 && w < n && j == 0) g_deg[w] = 0;
    if (warp == 0 && lane == 30) g_ticket = 0;
    if (group >= 6 || w >= n) return;

    int b  = g_off[w]     + g_bsum[w >> 10];
    int e2 = g_off[w + 1] + g_bsum[(w + 1) >> 10];
    float f0 = 0.f, f1 = 0.f, f2 = 0.f, f3 = 0.f;
    float f4 = 0.f, f5 = 0.f, f6 = 0.f, f7 = 0.f;
    const uint4* __restrict__ tb = (const uint4*)g_t;   // row = 8 uint4 (csr>>2)
    int i = b;
#pragma unroll 1
    for (; i + 1 < e2; i += 2) {
        int s0 = g_csr[i] >> 2, s1 = g_csr[i + 1] >> 2;
        uint4 r0 = tb[s0 + j];
        uint4 r1 = tb[s1 + j];
        const __half2* h0 = (const __half2*)&r0;
        const __half2* h1 = (const __half2*)&r1;
        float2 q0 = __half22float2(__hadd2(h0[0], h1[0]));
        float2 q1 = __half22float2(__hadd2(h0[1], h1[1]));
        float2 q2 = __half22float2(__hadd2(h0[2], h1[2]));
        float2 q3 = __half22float2(__hadd2(h0[3], h1[3]));
        f0 += q0.x; f1 += q0.y; f2 += q1.x; f3 += q1.y;
        f4 += q2.x; f5 += q2.y; f6 += q3.x; f7 += q3.y;
    }
    if (i < e2) {
        uint4 r0 = tb[(g_csr[i] >> 2) + j];
        const __half2* h0 = (const __half2*)&r0;
        float2 q0 = __half22float2(h0[0]);
        float2 q1 = __half22float2(h0[1]);
        float2 q2 = __half22float2(h0[2]);
        float2 q3 = __half22float2(h0[3]);
        f0 += q0.x; f1 += q0.y; f2 += q1.x; f3 += q1.y;
        f4 += q2.x; f5 += q2.y; f6 += q3.x; f7 += q3.y;
    }
    float inv = 1.0f / (float)max(e2 - b, 1);
    const float* sp = g_s + (size_t)w * 40 + j * 8;
    float4 s0 = *(const float4*)sp;
    float4 s1 = *(const float4*)(sp + 4);
    float4 o0, o1;
    o0.x = s0.x + f0 * inv; o0.y = s0.y + f1 * inv;
    o0.z = s0.z + f2 * inv; o0.w = s0.w + f3 * inv;
    o1.x = s1.x + f4 * inv; o1.y = s1.y + f5 * inv;
    o1.z = s1.z + f6 * inv; o1.w = s1.w + f7 * inv;
    float* op = out + (size_t)w * 40 + j * 8;
    *(float4*)op = o0;
    *(float4*)(op + 4) = o1;
}

// ---------------- launch (single stream) ----------------
extern "C" void kernel_launch(void* const* d_in, const int* in_sizes, int n_in,
                              void* d_out, int out_size) {
    const float* x   = (const float*)d_in[0];
    const int*   src = (const int*)  d_in[1];
    const int*   dst = (const int*)  d_in[2];
    const float* W1s = (const float*)d_in[3];
    const float* W1n = (const float*)d_in[4];
    const float* b1  = (const float*)d_in[5];
    const float* W2s = (const float*)d_in[6];
    const float* W2n = (const float*)d_in[7];
    const float* b2  = (const float*)d_in[8];
    float* out = (float*)d_out;

    const int E = in_sizes[1];
    const int N = in_sizes[0] / 128;
    const int nb = (N + 1023) / 1024;

    cudaFuncSetAttribute(k_gemm_fused, cudaFuncAttributeMaxDynamicSharedMemorySize, 98304);

    k_prep_count<<<(N * 32 + 255) / 256, 256>>>(x, W1s, W1n, W2s, W2n, dst, N, E);
    k_scan<<<nb, 1024>>>(nb, N);
    k_fill<<<(E + 255) / 256, 256>>>(src, dst, E);
    k_aggh<<<(N + 7) / 8, 256>>>(N);
    k_gemm_fused<<<(N + 127) / 128, 512, 98304>>>(b1, b2, N);
    k_agg40<<<((N + 5) / 6 * 32 + 255) / 256, 256>>>(out, N);
}